// round 1
// baseline (speedup 1.0000x reference)
#include <cuda_runtime.h>

// Problem constants
#define BV   8
#define CV   19
#define HWv  (512 * 1024)              // 524288 = 2^19
#define NPIX (BV * HWv)                // 4194304
#define THREADS 256
#define PIX_PER_THREAD 4
#define NBLOCKS (NPIX / (THREADS * PIX_PER_THREAD))   // 4096

__device__ float g_partials[NBLOCKS];

__global__ __launch_bounds__(THREADS)
void ce_main_kernel(const float* __restrict__ logits,
                    const int*   __restrict__ labels) {
    const int tid  = blockIdx.x * THREADS + threadIdx.x;
    const int base = tid * PIX_PER_THREAD;          // first pixel of this thread
    const int b    = base >> 19;                    // image index (HW = 2^19)
    const int pix  = base & (HWv - 1);              // pixel within image

    const float4* lp =
        reinterpret_cast<const float4*>(logits + (size_t)b * CV * HWv + pix);
    const int4 lab = *reinterpret_cast<const int4*>(labels + base);

    float4 s  = make_float4(0.f, 0.f, 0.f, 0.f);
    float4 xl = make_float4(0.f, 0.f, 0.f, 0.f);

    #pragma unroll
    for (int c = 0; c < CV; ++c) {
        const float4 v = lp[c * (HWv / 4)];
        s.x += __expf(v.x);
        s.y += __expf(v.y);
        s.z += __expf(v.z);
        s.w += __expf(v.w);
        if (c == lab.x) xl.x = v.x;
        if (c == lab.y) xl.y = v.y;
        if (c == lab.z) xl.z = v.z;
        if (c == lab.w) xl.w = v.w;
    }

    // nll = log(sum exp) - x_label ; zero at ignored pixels (label < 0)
    float loss = 0.f;
    loss += (lab.x >= 0) ? (__logf(s.x) - xl.x) : 0.f;
    loss += (lab.y >= 0) ? (__logf(s.y) - xl.y) : 0.f;
    loss += (lab.z >= 0) ? (__logf(s.z) - xl.z) : 0.f;
    loss += (lab.w >= 0) ? (__logf(s.w) - xl.w) : 0.f;

    // warp reduce
    #pragma unroll
    for (int o = 16; o > 0; o >>= 1)
        loss += __shfl_down_sync(0xFFFFFFFFu, loss, o);

    __shared__ float ws[THREADS / 32];
    if ((threadIdx.x & 31) == 0) ws[threadIdx.x >> 5] = loss;
    __syncthreads();

    if (threadIdx.x < (THREADS / 32)) {
        float v = ws[threadIdx.x];
        #pragma unroll
        for (int o = (THREADS / 64); o > 0; o >>= 1)
            v += __shfl_down_sync(0xFFu, v, o);
        if (threadIdx.x == 0) g_partials[blockIdx.x] = v;
    }
}

__global__ __launch_bounds__(1024)
void ce_reduce_kernel(float* __restrict__ out) {
    float s = 0.f;
    for (int i = threadIdx.x; i < NBLOCKS; i += 1024)
        s += g_partials[i];

    #pragma unroll
    for (int o = 16; o > 0; o >>= 1)
        s += __shfl_down_sync(0xFFFFFFFFu, s, o);

    __shared__ float ws[32];
    if ((threadIdx.x & 31) == 0) ws[threadIdx.x >> 5] = s;
    __syncthreads();

    if (threadIdx.x < 32) {
        float v = ws[threadIdx.x];
        #pragma unroll
        for (int o = 16; o > 0; o >>= 1)
            v += __shfl_down_sync(0xFFFFFFFFu, v, o);
        if (threadIdx.x == 0)
            out[0] = v * (1.0f / (float)NPIX);
    }
}

extern "C" void kernel_launch(void* const* d_in, const int* in_sizes, int n_in,
                              void* d_out, int out_size) {
    const float* logits = (const float*)d_in[0];
    const int*   labels = (const int*)d_in[1];
    // d_in[2] (smooth_labels) is dead in the reference forward — never read.
    float* out = (float*)d_out;

    ce_main_kernel<<<NBLOCKS, THREADS>>>(logits, labels);
    ce_reduce_kernel<<<1, 1024>>>(out);
}